// round 2
// baseline (speedup 1.0000x reference)
#include <cuda_runtime.h>

#define NN 5000
#define BB 64
#define CC 64
#define DD 10
#define JJ 4096   // BB*CC

// Scratch (device globals: allocation-free rule)
static __device__ float g_support[(size_t)NN * NN];   // 100 MB
static __device__ float g_xt[(size_t)NN * JJ];        // 81.9 MB  X transposed: [m][b*64+c]
static __device__ float g_y1[(size_t)NN * JJ];        // 81.9 MB  support @ Xt
static __device__ float g_et[DD * NN];                // E transposed [d][n]
static __device__ float g_rinv[NN];                   // 1/rowsum

// ---------------- E transpose ----------------
__global__ void k_transpose_e(const float* __restrict__ E) {
    int n = blockIdx.x * 256 + threadIdx.x;
    if (n < NN) {
#pragma unroll
        for (int d = 0; d < DD; d++) g_et[d * NN + n] = E[n * DD + d];
    }
}

// ---------------- X transpose: (B,N,C) -> (N, B*C) ----------------
__global__ void k_transpose_x(const float* __restrict__ x) {
    int m = blockIdx.y;
    int j = blockIdx.x * 256 + threadIdx.x;   // j = b*64 + c
    int b = j >> 6, c = j & 63;
    g_xt[(size_t)m * JJ + j] = x[((size_t)b * NN + m) * CC + c];
}

// ---------------- row sums of exp(relu(E E^T)) (no max-shift: logits <~ 40) ----------------
__global__ void k_rowsum() {
    __shared__ float se[DD];
    __shared__ float sred[256];
    int n = blockIdx.x, t = threadIdx.x;
    if (t < DD) se[t] = g_et[t * NN + n];
    __syncthreads();
    float s = 0.f;
    for (int m = t; m < NN; m += 256) {
        float dot = 0.f;
#pragma unroll
        for (int d = 0; d < DD; d++) dot += se[d] * g_et[d * NN + m];
        s += __expf(fmaxf(dot, 0.f));
    }
    sred[t] = s;
    __syncthreads();
    for (int off = 128; off > 0; off >>= 1) {
        if (t < off) sred[t] += sred[t + off];
        __syncthreads();
    }
    if (t == 0) g_rinv[n] = 1.f / sred[0];
}

// ---------------- materialize normalized support, 32n x 256m tiles ----------------
__global__ void k_support(const float* __restrict__ E) {
    __shared__ float sEm[DD][256];
    __shared__ float sEn[32][DD];
    __shared__ float srinv[32];
    int t = threadIdx.x;
    int m = blockIdx.x * 256 + t;
    int n0 = blockIdx.y * 32;
#pragma unroll
    for (int d = 0; d < DD; d++) sEm[d][t] = (m < NN) ? g_et[d * NN + m] : 0.f;
    for (int idx = t; idx < 32 * DD; idx += 256) {
        int ni = idx / DD, d = idx % DD;
        sEn[ni][d] = (n0 + ni < NN) ? E[(n0 + ni) * DD + d] : 0.f;
    }
    if (t < 32) srinv[t] = (n0 + t < NN) ? g_rinv[n0 + t] : 0.f;
    __syncthreads();
    if (m < NN) {
        int nmax = min(32, NN - n0);
        for (int ni = 0; ni < nmax; ni++) {
            float dot = 0.f;
#pragma unroll
            for (int d = 0; d < DD; d++) dot += sEn[ni][d] * sEm[d][t];
            g_support[(size_t)(n0 + ni) * NN + m] = __expf(fmaxf(dot, 0.f)) * srinv[ni];
        }
    }
}

// ---------------- fp32 SIMT GEMM: Y1[n,j] = sum_m support[n,m] * Xt[m,j] ----------------
// M=5000, N=4096, K=5000. 128x128x8 tiles, 8x8 microtile, 256 threads, reg-prefetch.
__global__ void __launch_bounds__(256) k_gemm() {
    __shared__ float As[8][128];
    __shared__ float Bs[8][128];
    int t = threadIdx.x;
    int m0 = blockIdx.y * 128, j0 = blockIdx.x * 128;
    int ty = t >> 4, tx = t & 15;
    int arow = t >> 1, acol = (t & 1) * 4;   // A tile 128x8
    int brow = t >> 5, bcol = (t & 31) * 4;  // B tile 8x128
    float acc[8][8];
#pragma unroll
    for (int i = 0; i < 8; i++)
#pragma unroll
        for (int j = 0; j < 8; j++) acc[i][j] = 0.f;

    const float* A = g_support;
    const float* Bm = g_xt;

    float4 av = make_float4(0.f, 0.f, 0.f, 0.f);
    if (m0 + arow < NN) av = __ldg((const float4*)(A + (size_t)(m0 + arow) * NN + acol));
    float4 bv = __ldg((const float4*)(Bm + (size_t)brow * JJ + j0 + bcol));

    for (int tk = 0; tk < NN; tk += 8) {
        As[acol + 0][arow] = av.x;
        As[acol + 1][arow] = av.y;
        As[acol + 2][arow] = av.z;
        As[acol + 3][arow] = av.w;
        *(float4*)&Bs[brow][bcol] = bv;
        __syncthreads();
        if (tk + 8 < NN) {
            av = make_float4(0.f, 0.f, 0.f, 0.f);
            if (m0 + arow < NN) av = __ldg((const float4*)(A + (size_t)(m0 + arow) * NN + (tk + 8) + acol));
            bv = __ldg((const float4*)(Bm + (size_t)(tk + 8 + brow) * JJ + j0 + bcol));
        }
#pragma unroll
        for (int kk = 0; kk < 8; kk++) {
            float ar[8], br[8];
#pragma unroll
            for (int i = 0; i < 4; i++) {
                ar[i]     = As[kk][ty * 4 + i];
                ar[4 + i] = As[kk][64 + ty * 4 + i];
            }
#pragma unroll
            for (int j = 0; j < 4; j++) {
                br[j]     = Bs[kk][tx * 4 + j];
                br[4 + j] = Bs[kk][64 + tx * 4 + j];
            }
#pragma unroll
            for (int i = 0; i < 8; i++)
#pragma unroll
                for (int j = 0; j < 8; j++) acc[i][j] += ar[i] * br[j];
        }
        __syncthreads();
    }
#pragma unroll
    for (int i = 0; i < 8; i++) {
        int row = m0 + ((i < 4) ? (ty * 4 + i) : (64 + ty * 4 + i - 4));
        if (row < NN) {
            float4 v0 = make_float4(acc[i][0], acc[i][1], acc[i][2], acc[i][3]);
            float4 v1 = make_float4(acc[i][4], acc[i][5], acc[i][6], acc[i][7]);
            *(float4*)(g_y1 + (size_t)row * JJ + j0 + tx * 4) = v0;
            *(float4*)(g_y1 + (size_t)row * JJ + j0 + 64 + tx * 4) = v1;
        }
    }
}

// ---------------- per-node epilogue: out[b,n,o] = sum_{k,i} xg[b,n,k,i] W[n,k,i,o] + bias[n,o] ----------------
__global__ void __launch_bounds__(256) k_out(const float* __restrict__ E,
                                             const float* __restrict__ pool,
                                             const float* __restrict__ bias_pool,
                                             float* __restrict__ out) {
    __shared__ float sW[64 * 64];
    __shared__ float sA[64 * 64];
    __shared__ float sbias[64];
    __shared__ float se[DD];
    int n = blockIdx.x, t = threadIdx.x;
    if (t < DD) se[t] = E[n * DD + t];
    __syncthreads();
    if (t < 64) {
        float b = 0.f;
#pragma unroll
        for (int d = 0; d < DD; d++) b += se[d] * bias_pool[d * 64 + t];
        sbias[t] = b;
    }
    __syncthreads();
    int ty = t >> 4, tx = t & 15;
    float acc[4][4];
#pragma unroll
    for (int r = 0; r < 4; r++)
#pragma unroll
        for (int c = 0; c < 4; c++) acc[r][c] = sbias[tx * 4 + c];

#pragma unroll
    for (int k = 0; k < 2; k++) {
        __syncthreads();   // protect sW/sA reuse
        // W[n,k,i,o] = sum_d e[d] * pool[d,k,i,o]
        for (int idx = t; idx < 4096; idx += 256) {
            int i = idx >> 6, o = idx & 63;
            float w = 0.f;
#pragma unroll
            for (int d = 0; d < DD; d++) w += se[d] * pool[((d * 2 + k) * 64 + i) * 64 + o];
            sW[idx] = w;
        }
        const float* src = (k == 0) ? g_xt : g_y1;
        for (int idx = t; idx < 4096; idx += 256) sA[idx] = src[(size_t)n * JJ + idx]; // sA[b*64+i]
        __syncthreads();
#pragma unroll 16
        for (int i = 0; i < 64; i++) {
            float a[4], w[4];
#pragma unroll
            for (int r = 0; r < 4; r++) a[r] = sA[(ty * 4 + r) * 64 + i];
#pragma unroll
            for (int c = 0; c < 4; c++) w[c] = sW[i * 64 + tx * 4 + c];
#pragma unroll
            for (int r = 0; r < 4; r++)
#pragma unroll
                for (int c = 0; c < 4; c++) acc[r][c] += a[r] * w[c];
        }
    }
#pragma unroll
    for (int r = 0; r < 4; r++) {
        int b = ty * 4 + r;
        float4 v = make_float4(acc[r][0], acc[r][1], acc[r][2], acc[r][3]);
        *(float4*)(out + ((size_t)b * NN + n) * CC + tx * 4) = v;
    }
}

extern "C" void kernel_launch(void* const* d_in, const int* in_sizes, int n_in,
                              void* d_out, int out_size) {
    const float* x         = (const float*)d_in[0];
    const float* E         = (const float*)d_in[1];
    const float* pool      = (const float*)d_in[2];
    const float* bias_pool = (const float*)d_in[3];
    float* out = (float*)d_out;

    k_transpose_e<<<(NN + 255) / 256, 256>>>(E);
    k_transpose_x<<<dim3(JJ / 256, NN), 256>>>(x);
    k_rowsum<<<NN, 256>>>();
    k_support<<<dim3((NN + 255) / 256, (NN + 31) / 32), 256>>>(E);
    k_gemm<<<dim3(JJ / 128, (NN + 127) / 128), 256>>>();
    k_out<<<NN, 256>>>(E, pool, bias_pool, out);
}

// round 4
// speedup vs baseline: 2.2085x; 2.2085x over previous
#include <cuda_runtime.h>
#include <cuda_bf16.h>
#include <cstdint>

#define NN 5000
#define KP 5120      // padded K/M dim (multiple of 128)
#define JJ 4096      // B*C
#define DD 10
#define CC 64

// ---- device-global scratch (allocation-free rule) ----
static __device__ __align__(16) __nv_bfloat16 g_ah[(size_t)KP * KP]; // support hi  [n][m]
static __device__ __align__(16) __nv_bfloat16 g_al[(size_t)KP * KP]; // support lo
static __device__ __align__(16) __nv_bfloat16 g_bh[(size_t)JJ * KP]; // B hi  [j][k] = x[b][k][c]
static __device__ __align__(16) __nv_bfloat16 g_bl[(size_t)JJ * KP]; // B lo
static __device__ float g_y1[(size_t)NN * JJ];                        // support @ X  [n][j]
static __device__ float g_et[DD * NN];
static __device__ float g_rinv[NN];

// ================= small prep kernels =================
__global__ void k_transpose_e(const float* __restrict__ E) {
    int n = blockIdx.x * 256 + threadIdx.x;
    if (n < NN) {
#pragma unroll
        for (int d = 0; d < DD; d++) g_et[d * NN + n] = E[n * DD + d];
    }
}

__global__ void k_rowsum() {
    __shared__ float se[DD];
    __shared__ float sred[256];
    int n = blockIdx.x, t = threadIdx.x;
    if (t < DD) se[t] = g_et[t * NN + n];
    __syncthreads();
    float s = 0.f;
    for (int m = t; m < NN; m += 256) {
        float dot = 0.f;
#pragma unroll
        for (int d = 0; d < DD; d++) dot += se[d] * g_et[d * NN + m];
        s += __expf(fmaxf(dot, 0.f));
    }
    sred[t] = s;
    __syncthreads();
    for (int off = 128; off > 0; off >>= 1) {
        if (t < off) sred[t] += sred[t + off];
        __syncthreads();
    }
    if (t == 0) g_rinv[n] = 1.f / sred[0];
}

// support -> bf16 hi/lo split, padded to KP x KP (zeros outside 5000x5000)
__global__ void k_support(const float* __restrict__ E) {
    __shared__ float sEm[DD][256];
    __shared__ float sEn[32][DD];
    __shared__ float srinv[32];
    int t = threadIdx.x;
    int m = blockIdx.x * 256 + t;       // m < KP
    int n0 = blockIdx.y * 32;           // n < KP
    bool mv = (m < NN);
#pragma unroll
    for (int d = 0; d < DD; d++) sEm[d][t] = mv ? g_et[d * NN + m] : 0.f;
    for (int idx = t; idx < 32 * DD; idx += 256) {
        int ni = idx / DD, d = idx % DD;
        sEn[ni][d] = (n0 + ni < NN) ? E[(n0 + ni) * DD + d] : 0.f;
    }
    if (t < 32) srinv[t] = (n0 + t < NN) ? g_rinv[n0 + t] : 0.f;
    __syncthreads();
    for (int ni = 0; ni < 32; ni++) {
        int n = n0 + ni;
        float v = 0.f;
        if (mv && n < NN) {
            float dot = 0.f;
#pragma unroll
            for (int d = 0; d < DD; d++) dot += sEn[ni][d] * sEm[d][t];
            v = __expf(fmaxf(dot, 0.f)) * srinv[ni];
        }
        __nv_bfloat16 h = __float2bfloat16_rn(v);
        __nv_bfloat16 l = __float2bfloat16_rn(v - __bfloat162float(h));
        g_ah[(size_t)n * KP + m] = h;
        g_al[(size_t)n * KP + m] = l;
    }
}

// x (B,N,C) -> bf16 hi/lo B operand [j][k], j=b*64+c, padded K
__global__ void k_conv_b(const float* __restrict__ x) {
    __shared__ float sx[64][65];
    int t = threadIdx.x;
    int j0 = blockIdx.x * 64;
    int k0 = blockIdx.y * 64;
    int b = j0 >> 6;
    for (int idx = t; idx < 4096; idx += 256) {
        int ky = idx >> 6, c = idx & 63;
        int k = k0 + ky;
        sx[ky][c] = (k < NN) ? x[((size_t)b * NN + k) * CC + c] : 0.f;
    }
    __syncthreads();
    for (int idx = t; idx < 4096; idx += 256) {
        int c = idx >> 6, ky = idx & 63;
        float v = sx[ky][c];
        __nv_bfloat16 h = __float2bfloat16_rn(v);
        __nv_bfloat16 l = __float2bfloat16_rn(v - __bfloat162float(h));
        size_t off = (size_t)(j0 + c) * KP + k0 + ky;
        g_bh[off] = h;
        g_bl[off] = l;
    }
}

// ================= mma.sync GEMM =================
// Y1[m][j] = sum_k support[m][k] * B[j][k]   via  ah*bh + ah*bl + al*bh
// 128x128x32 CTA tile, 8 warps (64x32 each), double-buffered cp.async,
// ldmatrix + mma.sync.m16n8k16 bf16, fp32 accumulate.
#define BK 32
#define ASTRIDE 80                 // 64B data + 16B pad per 32-bf16 row
#define TILE_SZ (128 * ASTRIDE)    // 10240 B
#define STAGE_SZ (4 * TILE_SZ)     // ah, al, bh, bl
#define SMEM_DYN (2 * STAGE_SZ)    // 81920 B
#define N_KC (KP / BK)             // 160

__device__ __forceinline__ void cp16(uint32_t dst, const void* gsrc) {
    asm volatile("cp.async.cg.shared.global [%0], [%1], 16;\n"
                 :: "r"(dst), "l"(__cvta_generic_to_global(gsrc)));
}
__device__ __forceinline__ void cp_commit() { asm volatile("cp.async.commit_group;\n" ::); }
__device__ __forceinline__ void cp_wait1() { asm volatile("cp.async.wait_group 1;\n" :: : "memory"); }

__device__ __forceinline__ void ldsm4(uint32_t* r, uint32_t addr) {
    asm volatile("ldmatrix.sync.aligned.m8n8.x4.shared.b16 {%0,%1,%2,%3}, [%4];\n"
                 : "=r"(r[0]), "=r"(r[1]), "=r"(r[2]), "=r"(r[3]) : "r"(addr));
}
__device__ __forceinline__ void mma16816(float* d, const uint32_t* a, uint32_t b0, uint32_t b1) {
    asm volatile(
        "mma.sync.aligned.m16n8k16.row.col.f32.bf16.bf16.f32 "
        "{%0,%1,%2,%3}, {%4,%5,%6,%7}, {%8,%9}, {%0,%1,%2,%3};\n"
        : "+f"(d[0]), "+f"(d[1]), "+f"(d[2]), "+f"(d[3])
        : "r"(a[0]), "r"(a[1]), "r"(a[2]), "r"(a[3]), "r"(b0), "r"(b1));
}

extern __shared__ __align__(128) char dsm[];

__device__ __forceinline__ void load_stage(uint32_t stage, int m0, int j0, int k0, int t) {
#pragma unroll
    for (int p = 0; p < 8; p++) {
        int i = p * 256 + t;
        int tile = i >> 9;          // 0..3 (ah, al, bh, bl)
        int rem = i & 511;
        int row = rem >> 2, c = rem & 3;
        const __nv_bfloat16* src = (tile == 0) ? g_ah : (tile == 1) ? g_al
                                  : (tile == 2) ? g_bh : g_bl;
        int r0 = (tile < 2) ? m0 : j0;
        cp16(stage + tile * TILE_SZ + row * ASTRIDE + c * 16,
             src + (size_t)(r0 + row) * KP + k0 + c * 8);
    }
}

__global__ void __launch_bounds__(256, 1) k_gemm_mma() {
    int t = threadIdx.x;
    int lane = t & 31, w = t >> 5;
    int m0 = blockIdx.y * 128, j0 = blockIdx.x * 128;
    int m0w = (w & 1) * 64;    // warp m-offset within tile
    int n0w = (w >> 1) * 32;   // warp n-offset within tile
    uint32_t sb = (uint32_t)__cvta_generic_to_shared(dsm);

    float acc[4][4][4];
#pragma unroll
    for (int mt = 0; mt < 4; mt++)
#pragma unroll
        for (int nt = 0; nt < 4; nt++)
#pragma unroll
            for (int q = 0; q < 4; q++) acc[mt][nt][q] = 0.f;

    // lane-invariant parts of ldmatrix addresses
    int aRow = m0w + (lane & 7) + ((lane >> 3) & 1) * 8;
    uint32_t aCol = ((lane >> 4) & 1) * 16;
    int bRow = n0w + (lane & 7) + ((lane >> 4) & 1) * 8;
    uint32_t bCol = ((lane >> 3) & 1) * 16;

    // prologue: stages 0,1
    load_stage(sb, m0, j0, 0, t);
    cp_commit();
    load_stage(sb + STAGE_SZ, m0, j0, BK, t);
    cp_commit();

    for (int kc = 0; kc < N_KC; kc++) {
        cp_wait1();
        __syncthreads();
        uint32_t st = sb + (kc & 1) * STAGE_SZ;
#pragma unroll
        for (int kh = 0; kh < 2; kh++) {
            uint32_t kOff = kh * 32;
            uint32_t ah[4][4], al[4][4], bh[2][4], bl[2][4];
#pragma unroll
            for (int mt = 0; mt < 4; mt++) {
                uint32_t rb = (aRow + mt * 16) * ASTRIDE + aCol + kOff;
                ldsm4(ah[mt], st + rb);
                ldsm4(al[mt], st + TILE_SZ + rb);
            }
#pragma unroll
            for (int pr = 0; pr < 2; pr++) {
                uint32_t rb = (bRow + pr * 16) * ASTRIDE + bCol + kOff;
                ldsm4(bh[pr], st + 2 * TILE_SZ + rb);
                ldsm4(bl[pr], st + 3 * TILE_SZ + rb);
            }
#pragma unroll
            for (int mt = 0; mt < 4; mt++)
#pragma unroll
                for (int nt = 0; nt < 4; nt++) {
                    uint32_t* bhp = bh[nt >> 1];
                    uint32_t* blp = bl[nt >> 1];
                    uint32_t b0h = bhp[(nt & 1) * 2], b1h = bhp[(nt & 1) * 2 + 1];
                    uint32_t b0l = blp[(nt & 1) * 2], b1l = blp[(nt & 1) * 2 + 1];
                    mma16816(acc[mt][nt], ah[mt], b0h, b1h);
                    mma16816(acc[mt][nt], ah[mt], b0l, b1l);
                    mma16816(acc[mt][nt], al[mt], b0h, b1h);
                }
        }
        __syncthreads();
        if (kc + 2 < N_KC) load_stage(sb + (kc & 1) * STAGE_SZ, m0, j0, (kc + 2) * BK, t);
        cp_commit();
    }

    // epilogue: fragment layout -> g_y1
    int g = lane >> 2, tig = lane & 3;
#pragma unroll
    for (int mt = 0; mt < 4; mt++) {
        int r0 = m0 + m0w + mt * 16 + g;
#pragma unroll
        for (int nt = 0; nt < 4; nt++) {
            int col = j0 + n0w + nt * 8 + tig * 2;
            if (r0 < NN)
                *(float2*)(g_y1 + (size_t)r0 * JJ + col) = make_float2(acc[mt][nt][0], acc[mt][nt][1]);
            if (r0 + 8 < NN)
                *(float2*)(g_y1 + (size_t)(r0 + 8) * JJ + col) = make_float2(acc[mt][nt][2], acc[mt][nt][3]);
        }
    }
}

// ================= per-node epilogue =================
__global__ void __launch_bounds__(256) k_out(const float* __restrict__ x,
                                             const float* __restrict__ E,
                                             const float* __restrict__ pool,
                                             const float* __restrict__ bias_pool,
                                             float* __restrict__ out) {
    __shared__ float sW[64 * 64];
    __shared__ float sA[64 * 64];
    __shared__ float sbias[64];
    __shared__ float se[DD];
    int n = blockIdx.x, t = threadIdx.x;
    if (t < DD) se[t] = E[n * DD + t];
    __syncthreads();
    if (t < 64) {
        float b = 0.f;
#pragma unroll
        for (int d = 0; d < DD; d++) b += se[d] * bias_pool[d * 64 + t];
        sbias[t] = b;
    }
    __syncthreads();
    int ty = t >> 4, tx = t & 15;
    float acc[4][4];
#pragma unroll
    for (int r = 0; r < 4; r++)
#pragma unroll
        for (int c = 0; c < 4; c++) acc[r][c] = sbias[tx * 4 + c];

#pragma unroll
    for (int k = 0; k < 2; k++) {
        __syncthreads();
        for (int idx = t; idx < 4096; idx += 256) {
            int i = idx >> 6, o = idx & 63;
            float w = 0.f;
#pragma unroll
            for (int d = 0; d < DD; d++) w += se[d] * pool[((d * 2 + k) * 64 + i) * 64 + o];
            sW[idx] = w;
        }
        if (k == 0) {
            for (int idx = t; idx < 4096; idx += 256) {
                int b = idx >> 6, c = idx & 63;
                sA[idx] = x[((size_t)b * NN + n) * CC + c];
            }
        } else {
            for (int idx = t; idx < 4096; idx += 256) sA[idx] = g_y1[(size_t)n * JJ + idx];
        }
        __syncthreads();
#pragma unroll 16
        for (int i = 0; i < 64; i++) {
            float a[4], wv[4];
#pragma unroll
            for (int r = 0; r < 4; r++) a[r] = sA[(ty * 4 + r) * 64 + i];
#pragma unroll
            for (int c = 0; c < 4; c++) wv[c] = sW[i * 64 + tx * 4 + c];
#pragma unroll
            for (int r = 0; r < 4; r++)
#pragma unroll
                for (int c = 0; c < 4; c++) acc[r][c] += a[r] * wv[c];
        }
    }
#pragma unroll
    for (int r = 0; r < 4; r++) {
        int b = ty * 4 + r;
        float4 v = make_float4(acc[r][0], acc[r][1], acc[r][2], acc[r][3]);
        *(float4*)(out + ((size_t)b * NN + n) * CC + tx * 4) = v;
    }
}

extern "C" void kernel_launch(void* const* d_in, const int* in_sizes, int n_in,
                              void* d_out, int out_size) {
    const float* x         = (const float*)d_in[0];
    const float* E         = (const float*)d_in[1];
    const float* pool      = (const float*)d_in[2];
    const float* bias_pool = (const float*)d_in[3];
    float* out = (float*)d_out;

    cudaFuncSetAttribute(k_gemm_mma, cudaFuncAttributeMaxDynamicSharedMemorySize, SMEM_DYN);

    k_transpose_e<<<(NN + 255) / 256, 256>>>(E);
    k_rowsum<<<NN, 256>>>();
    k_support<<<dim3(KP / 256, KP / 32), 256>>>(E);
    k_conv_b<<<dim3(JJ / 64, KP / 64), 256>>>(x);
    k_gemm_mma<<<dim3(JJ / 128, KP / 128), 256, SMEM_DYN>>>();
    k_out<<<NN, 256>>>(x, E, pool, bias_pool, out);
}

// round 5
// speedup vs baseline: 2.2373x; 1.0130x over previous
#include <cuda_runtime.h>
#include <cuda_bf16.h>
#include <cstdint>

#define NN 5000
#define KP 5120      // padded K/M dim (multiple of 128)
#define JJ 4096      // B*C
#define DD 10
#define CC 64

// ---- device-global scratch (allocation-free rule) ----
static __device__ __align__(16) __nv_bfloat16 g_ah[(size_t)KP * KP]; // support hi  [n][m]
static __device__ __align__(16) __nv_bfloat16 g_al[(size_t)KP * KP]; // support lo
static __device__ __align__(16) __nv_bfloat16 g_bh[(size_t)JJ * KP]; // B hi  [j][k] = x[b][k][c]
static __device__ __align__(16) __nv_bfloat16 g_bl[(size_t)JJ * KP]; // B lo
static __device__ float g_y1[(size_t)NN * JJ];                        // support @ X  [n][j]
static __device__ float g_et[DD * NN];
static __device__ float g_rinv[NN];

// ================= small prep kernels =================
__global__ void k_transpose_e(const float* __restrict__ E) {
    int n = blockIdx.x * 256 + threadIdx.x;
    if (n < NN) {
#pragma unroll
        for (int d = 0; d < DD; d++) g_et[d * NN + n] = E[n * DD + d];
    }
}

__global__ void k_rowsum() {
    __shared__ float se[DD];
    __shared__ float sred[256];
    int n = blockIdx.x, t = threadIdx.x;
    if (t < DD) se[t] = g_et[t * NN + n];
    __syncthreads();
    float s = 0.f;
    for (int m = t; m < NN; m += 256) {
        float dot = 0.f;
#pragma unroll
        for (int d = 0; d < DD; d++) dot += se[d] * g_et[d * NN + m];
        s += __expf(fmaxf(dot, 0.f));
    }
    sred[t] = s;
    __syncthreads();
    for (int off = 128; off > 0; off >>= 1) {
        if (t < off) sred[t] += sred[t + off];
        __syncthreads();
    }
    if (t == 0) g_rinv[n] = 1.f / sred[0];
}

// support -> bf16 hi/lo split, padded to KP x KP (zeros outside 5000x5000)
__global__ void k_support(const float* __restrict__ E) {
    __shared__ float sEm[DD][256];
    __shared__ float sEn[32][DD];
    __shared__ float srinv[32];
    int t = threadIdx.x;
    int m = blockIdx.x * 256 + t;       // m < KP
    int n0 = blockIdx.y * 32;           // n < KP
    bool mv = (m < NN);
#pragma unroll
    for (int d = 0; d < DD; d++) sEm[d][t] = mv ? g_et[d * NN + m] : 0.f;
    for (int idx = t; idx < 32 * DD; idx += 256) {
        int ni = idx / DD, d = idx % DD;
        sEn[ni][d] = (n0 + ni < NN) ? E[(n0 + ni) * DD + d] : 0.f;
    }
    if (t < 32) srinv[t] = (n0 + t < NN) ? g_rinv[n0 + t] : 0.f;
    __syncthreads();
    for (int ni = 0; ni < 32; ni++) {
        int n = n0 + ni;
        float v = 0.f;
        if (mv && n < NN) {
            float dot = 0.f;
#pragma unroll
            for (int d = 0; d < DD; d++) dot += sEn[ni][d] * sEm[d][t];
            v = __expf(fmaxf(dot, 0.f)) * srinv[ni];
        }
        __nv_bfloat16 h = __float2bfloat16_rn(v);
        __nv_bfloat16 l = __float2bfloat16_rn(v - __bfloat162float(h));
        g_ah[(size_t)n * KP + m] = h;
        g_al[(size_t)n * KP + m] = l;
    }
}

// x (B,N,C) -> bf16 hi/lo B operand [j][k], j=b*64+c, padded K
__global__ void k_conv_b(const float* __restrict__ x) {
    __shared__ float sx[64][65];
    int t = threadIdx.x;
    int j0 = blockIdx.x * 64;
    int k0 = blockIdx.y * 64;
    int b = j0 >> 6;
    for (int idx = t; idx < 4096; idx += 256) {
        int ky = idx >> 6, c = idx & 63;
        int k = k0 + ky;
        sx[ky][c] = (k < NN) ? x[((size_t)b * NN + k) * CC + c] : 0.f;
    }
    __syncthreads();
    for (int idx = t; idx < 4096; idx += 256) {
        int c = idx >> 6, ky = idx & 63;
        float v = sx[ky][c];
        __nv_bfloat16 h = __float2bfloat16_rn(v);
        __nv_bfloat16 l = __float2bfloat16_rn(v - __bfloat162float(h));
        size_t off = (size_t)(j0 + c) * KP + k0 + ky;
        g_bh[off] = h;
        g_bl[off] = l;
    }
}

// ================= mma.sync GEMM =================
// Y1[m][j] = sum_k support[m][k] * B[j][k]   via  ah*bh + ah*bl + al*bh
// 128x128x32 CTA tile, 8 warps (64x32 each), 4-stage cp.async ring,
// ldmatrix + mma.sync.m16n8k16 bf16, fp32 accumulate. One sync per chunk,
// loads issued before MMA (3-chunk prefetch depth).
#define BK 32
#define ASTRIDE 80                 // 64B data + 16B pad per 32-bf16 row
#define TILE_SZ (128 * ASTRIDE)    // 10240 B
#define STAGE_SZ (4 * TILE_SZ)     // ah, al, bh, bl = 40960 B
#define N_STG 4
#define SMEM_DYN (N_STG * STAGE_SZ)  // 163840 B
#define N_KC (KP / BK)             // 160

__device__ __forceinline__ void cp16(uint32_t dst, const void* gsrc) {
    asm volatile("cp.async.cg.shared.global [%0], [%1], 16;\n"
                 :: "r"(dst), "l"(__cvta_generic_to_global(gsrc)));
}
__device__ __forceinline__ void cp_commit() { asm volatile("cp.async.commit_group;\n" ::); }
__device__ __forceinline__ void cp_wait2() { asm volatile("cp.async.wait_group 2;\n" :: : "memory"); }

__device__ __forceinline__ void ldsm4(uint32_t* r, uint32_t addr) {
    asm volatile("ldmatrix.sync.aligned.m8n8.x4.shared.b16 {%0,%1,%2,%3}, [%4];\n"
                 : "=r"(r[0]), "=r"(r[1]), "=r"(r[2]), "=r"(r[3]) : "r"(addr));
}
__device__ __forceinline__ void mma16816(float* d, const uint32_t* a, uint32_t b0, uint32_t b1) {
    asm volatile(
        "mma.sync.aligned.m16n8k16.row.col.f32.bf16.bf16.f32 "
        "{%0,%1,%2,%3}, {%4,%5,%6,%7}, {%8,%9}, {%0,%1,%2,%3};\n"
        : "+f"(d[0]), "+f"(d[1]), "+f"(d[2]), "+f"(d[3])
        : "r"(a[0]), "r"(a[1]), "r"(a[2]), "r"(a[3]), "r"(b0), "r"(b1));
}

extern __shared__ __align__(128) char dsm[];

__device__ __forceinline__ void load_stage(uint32_t stage, int m0, int j0, int k0, int t) {
#pragma unroll
    for (int p = 0; p < 8; p++) {
        int i = p * 256 + t;
        int tile = i >> 9;          // 0..3 (ah, al, bh, bl)
        int rem = i & 511;
        int row = rem >> 2, c = rem & 3;
        const __nv_bfloat16* src = (tile == 0) ? g_ah : (tile == 1) ? g_al
                                  : (tile == 2) ? g_bh : g_bl;
        int r0 = (tile < 2) ? m0 : j0;
        cp16(stage + tile * TILE_SZ + row * ASTRIDE + c * 16,
             src + (size_t)(r0 + row) * KP + k0 + c * 8);
    }
}

__global__ void __launch_bounds__(256, 1) k_gemm_mma() {
    int t = threadIdx.x;
    int lane = t & 31, w = t >> 5;
    int m0 = blockIdx.y * 128, j0 = blockIdx.x * 128;
    int m0w = (w & 1) * 64;    // warp m-offset within tile
    int n0w = (w >> 1) * 32;   // warp n-offset within tile
    uint32_t sb = (uint32_t)__cvta_generic_to_shared(dsm);

    float acc[4][4][4];
#pragma unroll
    for (int mt = 0; mt < 4; mt++)
#pragma unroll
        for (int nt = 0; nt < 4; nt++)
#pragma unroll
            for (int q = 0; q < 4; q++) acc[mt][nt][q] = 0.f;

    // lane-invariant parts of ldmatrix addresses
    int aRow = m0w + (lane & 7) + ((lane >> 3) & 1) * 8;
    uint32_t aCol = ((lane >> 4) & 1) * 16;
    int bRow = n0w + (lane & 7) + ((lane >> 4) & 1) * 8;
    uint32_t bCol = ((lane >> 3) & 1) * 16;

    // prologue: stages 0..2 hold chunks 0..2
#pragma unroll
    for (int c = 0; c < 3; c++) {
        load_stage(sb + c * STAGE_SZ, m0, j0, c * BK, t);
        cp_commit();
    }

    for (int kc = 0; kc < N_KC; kc++) {
        cp_wait2();        // chunk kc resident (<=2 younger groups pending)
        __syncthreads();   // all warps done reading stage (kc+3)%4 (iter kc-1)

        // prefetch chunk kc+3 into the stage freed at iter kc-1
        if (kc + 3 < N_KC)
            load_stage(sb + ((kc + 3) % N_STG) * STAGE_SZ, m0, j0, (kc + 3) * BK, t);
        cp_commit();       // always commit: keeps wait_group accounting uniform

        uint32_t st = sb + (kc % N_STG) * STAGE_SZ;
#pragma unroll
        for (int kh = 0; kh < 2; kh++) {
            uint32_t kOff = kh * 32;
            uint32_t ah[4][4], al[4][4], bh[2][4], bl[2][4];
#pragma unroll
            for (int mt = 0; mt < 4; mt++) {
                uint32_t rb = (aRow + mt * 16) * ASTRIDE + aCol + kOff;
                ldsm4(ah[mt], st + rb);
                ldsm4(al[mt], st + TILE_SZ + rb);
            }
#pragma unroll
            for (int pr = 0; pr < 2; pr++) {
                uint32_t rb = (bRow + pr * 16) * ASTRIDE + bCol + kOff;
                ldsm4(bh[pr], st + 2 * TILE_SZ + rb);
                ldsm4(bl[pr], st + 3 * TILE_SZ + rb);
            }
#pragma unroll
            for (int mt = 0; mt < 4; mt++)
#pragma unroll
                for (int nt = 0; nt < 4; nt++) {
                    uint32_t* bhp = bh[nt >> 1];
                    uint32_t* blp = bl[nt >> 1];
                    uint32_t b0h = bhp[(nt & 1) * 2], b1h = bhp[(nt & 1) * 2 + 1];
                    uint32_t b0l = blp[(nt & 1) * 2], b1l = blp[(nt & 1) * 2 + 1];
                    mma16816(acc[mt][nt], ah[mt], b0h, b1h);
                    mma16816(acc[mt][nt], ah[mt], b0l, b1l);
                    mma16816(acc[mt][nt], al[mt], b0h, b1h);
                }
        }
    }

    // epilogue: fragment layout -> g_y1
    int g = lane >> 2, tig = lane & 3;
#pragma unroll
    for (int mt = 0; mt < 4; mt++) {
        int r0 = m0 + m0w + mt * 16 + g;
#pragma unroll
        for (int nt = 0; nt < 4; nt++) {
            int col = j0 + n0w + nt * 8 + tig * 2;
            if (r0 < NN)
                *(float2*)(g_y1 + (size_t)r0 * JJ + col) = make_float2(acc[mt][nt][0], acc[mt][nt][1]);
            if (r0 + 8 < NN)
                *(float2*)(g_y1 + (size_t)(r0 + 8) * JJ + col) = make_float2(acc[mt][nt][2], acc[mt][nt][3]);
        }
    }
}

// ================= per-node epilogue =================
__global__ void __launch_bounds__(256) k_out(const float* __restrict__ x,
                                             const float* __restrict__ E,
                                             const float* __restrict__ pool,
                                             const float* __restrict__ bias_pool,
                                             float* __restrict__ out) {
    __shared__ float sW[64 * 64];
    __shared__ float sA[64 * 64];
    __shared__ float sbias[64];
    __shared__ float se[DD];
    int n = blockIdx.x, t = threadIdx.x;
    if (t < DD) se[t] = E[n * DD + t];
    __syncthreads();
    if (t < 64) {
        float b = 0.f;
#pragma unroll
        for (int d = 0; d < DD; d++) b += se[d] * bias_pool[d * 64 + t];
        sbias[t] = b;
    }
    __syncthreads();
    int ty = t >> 4, tx = t & 15;
    float acc[4][4];
#pragma unroll
    for (int r = 0; r < 4; r++)
#pragma unroll
        for (int c = 0; c < 4; c++) acc[r][c] = sbias[tx * 4 + c];

#pragma unroll
    for (int k = 0; k < 2; k++) {
        __syncthreads();
        for (int idx = t; idx < 4096; idx += 256) {
            int i = idx >> 6, o = idx & 63;
            float w = 0.f;
#pragma unroll
            for (int d = 0; d < DD; d++) w += se[d] * pool[((d * 2 + k) * 64 + i) * 64 + o];
            sW[idx] = w;
        }
        if (k == 0) {
            for (int idx = t; idx < 4096; idx += 256) {
                int b = idx >> 6, c = idx & 63;
                sA[idx] = x[((size_t)b * NN + n) * CC + c];
            }
        } else {
            for (int idx = t; idx < 4096; idx += 256) sA[idx] = g_y1[(size_t)n * JJ + idx];
        }
        __syncthreads();
#pragma unroll 16
        for (int i = 0; i < 64; i++) {
            float a[4], wv[4];
#pragma unroll
            for (int r = 0; r < 4; r++) a[r] = sA[(ty * 4 + r) * 64 + i];
#pragma unroll
            for (int c = 0; c < 4; c++) wv[c] = sW[i * 64 + tx * 4 + c];
#pragma unroll
            for (int r = 0; r < 4; r++)
#pragma unroll
                for (int c = 0; c < 4; c++) acc[r][c] += a[r] * wv[c];
        }
    }
#pragma unroll
    for (int r = 0; r < 4; r++) {
        int b = ty * 4 + r;
        float4 v = make_float4(acc[r][0], acc[r][1], acc[r][2], acc[r][3]);
        *(float4*)(out + ((size_t)b * NN + n) * CC + tx * 4) = v;
    }
}

extern "C" void kernel_launch(void* const* d_in, const int* in_sizes, int n_in,
                              void* d_out, int out_size) {
    const float* x         = (const float*)d_in[0];
    const float* E         = (const float*)d_in[1];
    const float* pool      = (const float*)d_in[2];
    const float* bias_pool = (const float*)d_in[3];
    float* out = (float*)d_out;

    cudaFuncSetAttribute(k_gemm_mma, cudaFuncAttributeMaxDynamicSharedMemorySize, SMEM_DYN);

    k_transpose_e<<<(NN + 255) / 256, 256>>>(E);
    k_rowsum<<<NN, 256>>>();
    k_support<<<dim3(KP / 256, KP / 32), 256>>>(E);
    k_conv_b<<<dim3(JJ / 64, KP / 64), 256>>>(x);
    k_gemm_mma<<<dim3(JJ / 128, KP / 128), 256, SMEM_DYN>>>();
    k_out<<<NN, 256>>>(x, E, pool, bias_pool, out);
}

// round 6
// speedup vs baseline: 4.8934x; 2.1872x over previous
#include <cuda_runtime.h>
#include <cuda_fp16.h>
#include <cstdint>

#define NN 5000
#define KP 5120      // padded K/M dim (multiple of 128)
#define JJ 4096      // B*C
#define DD 10
#define CC 64

// ---- device-global scratch (allocation-free rule) ----
static __device__ __align__(16) __half g_sh[(size_t)KP * KP]; // support fp16 [n][m]
static __device__ __align__(16) __half g_xh[(size_t)JJ * KP]; // X fp16 [j][k] = x[b][k][c]
static __device__ float g_y1[(size_t)NN * JJ];                 // support @ X  [n][j]
static __device__ float g_et[DD * NN];
static __device__ float g_rinv[NN];

// ================= small prep kernels =================
__global__ void k_transpose_e(const float* __restrict__ E) {
    int n = blockIdx.x * 256 + threadIdx.x;
    if (n < NN) {
#pragma unroll
        for (int d = 0; d < DD; d++) g_et[d * NN + n] = E[n * DD + d];
    }
}

__global__ void k_rowsum() {
    __shared__ float se[DD];
    __shared__ float sred[256];
    int n = blockIdx.x, t = threadIdx.x;
    if (t < DD) se[t] = g_et[t * NN + n];
    __syncthreads();
    float s = 0.f;
    for (int m = t; m < NN; m += 256) {
        float dot = 0.f;
#pragma unroll
        for (int d = 0; d < DD; d++) dot += se[d] * g_et[d * NN + m];
        s += __expf(fmaxf(dot, 0.f));
    }
    sred[t] = s;
    __syncthreads();
    for (int off = 128; off > 0; off >>= 1) {
        if (t < off) sred[t] += sred[t + off];
        __syncthreads();
    }
    if (t == 0) g_rinv[n] = 1.f / sred[0];
}

// support -> fp16, padded to KP x KP (zeros outside 5000x5000)
__global__ void k_support(const float* __restrict__ E) {
    __shared__ float sEm[DD][256];
    __shared__ float sEn[32][DD];
    __shared__ float srinv[32];
    int t = threadIdx.x;
    int m = blockIdx.x * 256 + t;       // m < KP
    int n0 = blockIdx.y * 32;           // n < KP
    bool mv = (m < NN);
#pragma unroll
    for (int d = 0; d < DD; d++) sEm[d][t] = mv ? g_et[d * NN + m] : 0.f;
    for (int idx = t; idx < 32 * DD; idx += 256) {
        int ni = idx / DD, d = idx % DD;
        sEn[ni][d] = (n0 + ni < NN) ? E[(n0 + ni) * DD + d] : 0.f;
    }
    if (t < 32) srinv[t] = (n0 + t < NN) ? g_rinv[n0 + t] : 0.f;
    __syncthreads();
    for (int ni = 0; ni < 32; ni++) {
        int n = n0 + ni;
        float v = 0.f;
        if (mv && n < NN) {
            float dot = 0.f;
#pragma unroll
            for (int d = 0; d < DD; d++) dot += sEn[ni][d] * sEm[d][t];
            v = __expf(fmaxf(dot, 0.f)) * srinv[ni];
        }
        g_sh[(size_t)n * KP + m] = __float2half_rn(v);
    }
}

// x (B,N,C) -> fp16 [j][k], j=b*64+c, padded K
__global__ void k_conv_b(const float* __restrict__ x) {
    __shared__ float sx[64][65];
    int t = threadIdx.x;
    int j0 = blockIdx.x * 64;
    int k0 = blockIdx.y * 64;
    int b = j0 >> 6;
    for (int idx = t; idx < 4096; idx += 256) {
        int ky = idx >> 6, c = idx & 63;
        int k = k0 + ky;
        sx[ky][c] = (k < NN) ? x[((size_t)b * NN + k) * CC + c] : 0.f;
    }
    __syncthreads();
    for (int idx = t; idx < 4096; idx += 256) {
        int c = idx >> 6, ky = idx & 63;
        g_xh[(size_t)(j0 + c) * KP + k0 + ky] = __float2half_rn(sx[ky][c]);
    }
}

// ================= mma.sync GEMM (single-pass fp16) =================
// Y1[m][j] = sum_k support[m][k] * X[j][k]
// 128x128x32 CTA tile, 8 warps (64x32 each), 4-stage cp.async ring.
#define BK 32
#define ASTRIDE 80                 // 64B data + 16B pad per 32-fp16 row
#define TILE_SZ (128 * ASTRIDE)    // 10240 B
#define STAGE_SZ (2 * TILE_SZ)     // S, X = 20480 B
#define N_STG 4
#define SMEM_DYN (N_STG * STAGE_SZ)  // 81920 B
#define N_KC (KP / BK)             // 160

__device__ __forceinline__ void cp16(uint32_t dst, const void* gsrc) {
    asm volatile("cp.async.cg.shared.global [%0], [%1], 16;\n"
                 :: "r"(dst), "l"(__cvta_generic_to_global(gsrc)));
}
__device__ __forceinline__ void cp_commit() { asm volatile("cp.async.commit_group;\n" ::); }
__device__ __forceinline__ void cp_wait2() { asm volatile("cp.async.wait_group 2;\n" :: : "memory"); }

__device__ __forceinline__ void ldsm4(uint32_t* r, uint32_t addr) {
    asm volatile("ldmatrix.sync.aligned.m8n8.x4.shared.b16 {%0,%1,%2,%3}, [%4];\n"
                 : "=r"(r[0]), "=r"(r[1]), "=r"(r[2]), "=r"(r[3]) : "r"(addr));
}
__device__ __forceinline__ void mma16816(float* d, const uint32_t* a, uint32_t b0, uint32_t b1) {
    asm volatile(
        "mma.sync.aligned.m16n8k16.row.col.f32.f16.f16.f32 "
        "{%0,%1,%2,%3}, {%4,%5,%6,%7}, {%8,%9}, {%0,%1,%2,%3};\n"
        : "+f"(d[0]), "+f"(d[1]), "+f"(d[2]), "+f"(d[3])
        : "r"(a[0]), "r"(a[1]), "r"(a[2]), "r"(a[3]), "r"(b0), "r"(b1));
}

extern __shared__ __align__(128) char dsm[];

__device__ __forceinline__ void load_stage(uint32_t stage, int m0, int j0, int k0, int t) {
#pragma unroll
    for (int p = 0; p < 4; p++) {
        int i = p * 256 + t;        // 0..1023
        int tile = i >> 9;          // 0: S, 1: X
        int rem = i & 511;
        int row = rem >> 2, c = rem & 3;
        const __half* src = (tile == 0) ? g_sh : g_xh;
        int r0 = (tile == 0) ? m0 : j0;
        cp16(stage + tile * TILE_SZ + row * ASTRIDE + c * 16,
             src + (size_t)(r0 + row) * KP + k0 + c * 8);
    }
}

__global__ void __launch_bounds__(256, 2) k_gemm_mma() {
    int t = threadIdx.x;
    int lane = t & 31, w = t >> 5;
    int m0 = blockIdx.y * 128, j0 = blockIdx.x * 128;
    int m0w = (w & 1) * 64;    // warp m-offset within tile
    int n0w = (w >> 1) * 32;   // warp n-offset within tile
    uint32_t sb = (uint32_t)__cvta_generic_to_shared(dsm);

    float acc[4][4][4];
#pragma unroll
    for (int mt = 0; mt < 4; mt++)
#pragma unroll
        for (int nt = 0; nt < 4; nt++)
#pragma unroll
            for (int q = 0; q < 4; q++) acc[mt][nt][q] = 0.f;

    // lane-invariant parts of ldmatrix addresses
    int aRow = m0w + (lane & 7) + ((lane >> 3) & 1) * 8;
    uint32_t aCol = ((lane >> 4) & 1) * 16;
    int bRow = n0w + (lane & 7) + ((lane >> 4) & 1) * 8;
    uint32_t bCol = ((lane >> 3) & 1) * 16;

    // prologue: stages 0..2 hold chunks 0..2
#pragma unroll
    for (int c = 0; c < 3; c++) {
        load_stage(sb + c * STAGE_SZ, m0, j0, c * BK, t);
        cp_commit();
    }

    for (int kc = 0; kc < N_KC; kc++) {
        cp_wait2();        // chunk kc resident
        __syncthreads();   // all warps done reading stage (kc+3)%4

        if (kc + 3 < N_KC)
            load_stage(sb + ((kc + 3) % N_STG) * STAGE_SZ, m0, j0, (kc + 3) * BK, t);
        cp_commit();

        uint32_t st = sb + (kc % N_STG) * STAGE_SZ;
#pragma unroll
        for (int kh = 0; kh < 2; kh++) {
            uint32_t kOff = kh * 32;
            uint32_t a[4][4], b[2][4];
#pragma unroll
            for (int mt = 0; mt < 4; mt++)
                ldsm4(a[mt], st + (aRow + mt * 16) * ASTRIDE + aCol + kOff);
#pragma unroll
            for (int pr = 0; pr < 2; pr++)
                ldsm4(b[pr], st + TILE_SZ + (bRow + pr * 16) * ASTRIDE + bCol + kOff);
#pragma unroll
            for (int mt = 0; mt < 4; mt++)
#pragma unroll
                for (int nt = 0; nt < 4; nt++) {
                    uint32_t* bp = b[nt >> 1];
                    mma16816(acc[mt][nt], a[mt], bp[(nt & 1) * 2], bp[(nt & 1) * 2 + 1]);
                }
        }
    }

    // epilogue: fragment layout -> g_y1
    int g = lane >> 2, tig = lane & 3;
#pragma unroll
    for (int mt = 0; mt < 4; mt++) {
        int r0 = m0 + m0w + mt * 16 + g;
#pragma unroll
        for (int nt = 0; nt < 4; nt++) {
            int col = j0 + n0w + nt * 8 + tig * 2;
            if (r0 < NN)
                *(float2*)(g_y1 + (size_t)r0 * JJ + col) = make_float2(acc[mt][nt][0], acc[mt][nt][1]);
            if (r0 + 8 < NN)
                *(float2*)(g_y1 + (size_t)(r0 + 8) * JJ + col) = make_float2(acc[mt][nt][2], acc[mt][nt][3]);
        }
    }
}

// ================= per-node epilogue =================
__global__ void __launch_bounds__(256) k_out(const float* __restrict__ x,
                                             const float* __restrict__ E,
                                             const float* __restrict__ pool,
                                             const float* __restrict__ bias_pool,
                                             float* __restrict__ out) {
    __shared__ float sW[64 * 64];
    __shared__ float sA[64 * 64];
    __shared__ float sbias[64];
    __shared__ float se[DD];
    int n = blockIdx.x, t = threadIdx.x;
    if (t < DD) se[t] = E[n * DD + t];
    __syncthreads();
    if (t < 64) {
        float b = 0.f;
#pragma unroll
        for (int d = 0; d < DD; d++) b += se[d] * bias_pool[d * 64 + t];
        sbias[t] = b;
    }
    __syncthreads();
    int ty = t >> 4, tx = t & 15;
    float acc[4][4];
#pragma unroll
    for (int r = 0; r < 4; r++)
#pragma unroll
        for (int c = 0; c < 4; c++) acc[r][c] = sbias[tx * 4 + c];

#pragma unroll
    for (int k = 0; k < 2; k++) {
        __syncthreads();
        for (int idx = t; idx < 4096; idx += 256) {
            int i = idx >> 6, o = idx & 63;
            float w = 0.f;
#pragma unroll
            for (int d = 0; d < DD; d++) w += se[d] * pool[((d * 2 + k) * 64 + i) * 64 + o];
            sW[idx] = w;
        }
        if (k == 0) {
            for (int idx = t; idx < 4096; idx += 256) {
                int b = idx >> 6, c = idx & 63;
                sA[idx] = x[((size_t)b * NN + n) * CC + c];
            }
        } else {
            for (int idx = t; idx < 4096; idx += 256) sA[idx] = g_y1[(size_t)n * JJ + idx];
        }
        __syncthreads();
#pragma unroll 16
        for (int i = 0; i < 64; i++) {
            float a[4], wv[4];
#pragma unroll
            for (int r = 0; r < 4; r++) a[r] = sA[(ty * 4 + r) * 64 + i];
#pragma unroll
            for (int c = 0; c < 4; c++) wv[c] = sW[i * 64 + tx * 4 + c];
#pragma unroll
            for (int r = 0; r < 4; r++)
#pragma unroll
                for (int c = 0; c < 4; c++) acc[r][c] += a[r] * wv[c];
        }
    }
#pragma unroll
    for (int r = 0; r < 4; r++) {
        int b = ty * 4 + r;
        float4 v = make_float4(acc[r][0], acc[r][1], acc[r][2], acc[r][3]);
        *(float4*)(out + ((size_t)b * NN + n) * CC + tx * 4) = v;
    }
}

extern "C" void kernel_launch(void* const* d_in, const int* in_sizes, int n_in,
                              void* d_out, int out_size) {
    const float* x         = (const float*)d_in[0];
    const float* E         = (const float*)d_in[1];
    const float* pool      = (const float*)d_in[2];
    const float* bias_pool = (const float*)d_in[3];
    float* out = (float*)d_out;

    cudaFuncSetAttribute(k_gemm_mma, cudaFuncAttributeMaxDynamicSharedMemorySize, SMEM_DYN);

    k_transpose_e<<<(NN + 255) / 256, 256>>>(E);
    k_rowsum<<<NN, 256>>>();
    k_support<<<dim3(KP / 256, KP / 32), 256>>>(E);
    k_conv_b<<<dim3(JJ / 64, KP / 64), 256>>>(x);
    k_gemm_mma<<<dim3(JJ / 128, KP / 128), 256, SMEM_DYN>>>();
    k_out<<<NN, 256>>>(x, E, pool, bias_pool, out);
}